// round 5
// baseline (speedup 1.0000x reference)
#include <cuda_runtime.h>
#include <math.h>

#define NN   20000        // nodes
#define NE   320000       // edges (without self loops)
#define ETOT (NE + NN)    // edges + self loops
#define NGR  256          // graphs
#define FD   11           // node feature dim
#define FT   30           // tda feature dim
#define DH   128          // hidden
#define NH   4            // heads
#define NL   3            // layers
#define NT   6            // tasks

// ---------------- device scratch (static, no allocations) ----------------
// Referenced ONLY inside kernels — never passed as kernel arguments.
__device__ float  g_h[NN * DH];            // node features (in-place updated)
__device__ float  g_hh[NN * NH * DH];      // per-head transformed features [N,512]
__device__ float  g_as[NN * NH];           // alpha_src per node/head
__device__ float  g_ad[NN * NH];           // alpha_dst per node/head
__device__ int    g_rowptr[NN + 1];
__device__ int    g_cnt[NN];               // counts, then scatter cursor
__device__ int    g_esrc[ETOT];            // src ids sorted by dst
__device__ int    g_gstart[NGR + 1];
__device__ float  g_pool[NGR * 320];       // [mean(128) | max(128) | tda(64)]

// ---------------- tf32 mma helpers ----------------
__device__ __forceinline__ void mma_tf32(float c[4], const unsigned a[4], const unsigned b[2]) {
    asm volatile(
        "mma.sync.aligned.m16n8k8.row.col.f32.tf32.tf32.f32 "
        "{%0,%1,%2,%3}, {%4,%5,%6,%7}, {%8,%9}, {%0,%1,%2,%3};\n"
        : "+f"(c[0]), "+f"(c[1]), "+f"(c[2]), "+f"(c[3])
        : "r"(a[0]), "r"(a[1]), "r"(a[2]), "r"(a[3]), "r"(b[0]), "r"(b[1]));
}

__device__ __forceinline__ void split_tf32(float x, unsigned& hi, unsigned& lo) {
    unsigned h_;
    asm("cvt.rna.tf32.f32 %0, %1;" : "=r"(h_) : "f"(x));
    float l = x - __uint_as_float(h_);
    unsigned l_;
    asm("cvt.rna.tf32.f32 %0, %1;" : "=r"(l_) : "f"(l));
    hi = h_; lo = l_;
}

// ---------------- CSR build ----------------
__global__ void k_prep(const int* __restrict__ batch) {
    int i = blockIdx.x * blockDim.x + threadIdx.x;
    if (i < NN) g_cnt[i] = 0;
    if (i <= NN) {
        int b  = (i < NN) ? batch[i] : NGR;
        int bp = (i > 0) ? batch[i - 1] : -1;
        for (int g = bp + 1; g <= b && g <= NGR; g++) g_gstart[g] = i;
    }
}

__global__ void k_count(const int* __restrict__ ei) {
    int i = blockIdx.x * blockDim.x + threadIdx.x;
    if (i >= ETOT) return;
    int dst = (i < NE) ? ei[NE + i] : (i - NE);
    atomicAdd(&g_cnt[dst], 1);
}

__global__ void k_scan() {   // single block, 1024 threads, chunk=20; also writes cursor
    __shared__ int ssum[1024];
    const int CH = 20;
    int tid = threadIdx.x;
    int base = tid * CH;
    int s = 0;
    for (int j = 0; j < CH; j++) {
        int idx = base + j;
        if (idx < NN) s += g_cnt[idx];
    }
    ssum[tid] = s;
    __syncthreads();
    for (int off = 1; off < 1024; off <<= 1) {
        int v = 0;
        if (tid >= off) v = ssum[tid - off];
        __syncthreads();
        ssum[tid] += v;
        __syncthreads();
    }
    int run = tid ? ssum[tid - 1] : 0;
    for (int j = 0; j < CH; j++) {
        int idx = base + j;
        if (idx < NN) {
            int c = g_cnt[idx];
            g_rowptr[idx] = run;
            g_cnt[idx]    = run;   // scatter cursor
            run += c;
        }
    }
    if (tid == 1023) g_rowptr[NN] = ssum[1023];
}

__global__ void k_scatter(const int* __restrict__ ei) {
    int i = blockIdx.x * blockDim.x + threadIdx.x;
    if (i >= ETOT) return;
    int src, dst;
    if (i < NE) { src = ei[i]; dst = ei[NE + i]; }
    else        { src = i - NE; dst = i - NE; }
    int pos = atomicAdd(&g_cnt[dst], 1);
    g_esrc[pos] = src;
}

// ---------------- input projection: h = relu(x @ w_in + b_in) ----------------
__global__ void k_inproj(const float* __restrict__ x, const float* __restrict__ w,
                         const float* __restrict__ b) {
    int n = blockIdx.x, d = threadIdx.x;
    __shared__ float xs[FD];
    if (d < FD) xs[d] = x[n * FD + d];
    __syncthreads();
    float a = b[d];
#pragma unroll
    for (int k = 0; k < FD; k++) a += xs[k] * w[k * DH + d];
    g_h[n * DH + d] = fmaxf(a, 0.f);
}

// ---------------- tf32 tensor-core GEMM + fused alpha dots ----------------
// block: 128 rows x one head (128 cols). grid (157, 4). 256 threads = 8 warps (4m x 2n).
__global__ __launch_bounds__(256) void k_gemm_tc(const float* __restrict__ B,
                                                 const float* __restrict__ aw_s,
                                                 const float* __restrict__ aw_d) {
    __shared__ float As[128][36];
    __shared__ float Bs[32][132];
    __shared__ float s_as[128], s_ad[128];
    __shared__ float abuf[2][2][128];   // [s/d][warp_n][row]

    int tid = threadIdx.x;
    int wid = tid >> 5, lane = tid & 31;
    int warp_m = wid & 3, warp_n = wid >> 2;
    int m0 = blockIdx.x * 128;
    int h  = blockIdx.y;
    int g  = lane >> 2, t = lane & 3;

    if (tid < 128) { s_as[tid] = aw_s[h * 128 + tid]; s_ad[tid] = aw_d[h * 128 + tid]; }

    float c[2][8][4];
#pragma unroll
    for (int mt = 0; mt < 2; mt++)
#pragma unroll
        for (int nt = 0; nt < 8; nt++)
#pragma unroll
            for (int i = 0; i < 4; i++) c[mt][nt][i] = 0.f;

    int ar = tid >> 1, akg = (tid & 1) * 16;
    int bkr = tid >> 3, bcg = (tid & 7) * 16;

    for (int kc = 0; kc < 128; kc += 32) {
        __syncthreads();
        if (m0 + ar < NN) {
#pragma unroll
            for (int j = 0; j < 4; j++)
                *(float4*)&As[ar][akg + j * 4] =
                    *(const float4*)&g_h[(m0 + ar) * 128 + kc + akg + j * 4];
        } else {
            float4 z = make_float4(0.f, 0.f, 0.f, 0.f);
#pragma unroll
            for (int j = 0; j < 4; j++) *(float4*)&As[ar][akg + j * 4] = z;
        }
#pragma unroll
        for (int j = 0; j < 4; j++)
            *(float4*)&Bs[bkr][bcg + j * 4] =
                *(const float4*)&B[(kc + bkr) * 512 + h * 128 + bcg + j * 4];
        __syncthreads();

#pragma unroll
        for (int kk = 0; kk < 32; kk += 8) {
            unsigned ah[2][4], al[2][4];
#pragma unroll
            for (int mt = 0; mt < 2; mt++) {
                int rb = warp_m * 32 + mt * 16;
                float a0 = As[rb + g][kk + t];
                float a1 = As[rb + g + 8][kk + t];
                float a2 = As[rb + g][kk + t + 4];
                float a3 = As[rb + g + 8][kk + t + 4];
                split_tf32(a0, ah[mt][0], al[mt][0]);
                split_tf32(a1, ah[mt][1], al[mt][1]);
                split_tf32(a2, ah[mt][2], al[mt][2]);
                split_tf32(a3, ah[mt][3], al[mt][3]);
            }
#pragma unroll
            for (int nt = 0; nt < 8; nt++) {
                int cb = warp_n * 64 + nt * 8;
                float b0 = Bs[kk + t][cb + g];
                float b1 = Bs[kk + t + 4][cb + g];
                unsigned bh[2], bl[2];
                split_tf32(b0, bh[0], bl[0]);
                split_tf32(b1, bh[1], bl[1]);
#pragma unroll
                for (int mt = 0; mt < 2; mt++) {
                    mma_tf32(c[mt][nt], ah[mt], bh);
                    mma_tf32(c[mt][nt], ah[mt], bl);
                    mma_tf32(c[mt][nt], al[mt], bh);
                }
            }
        }
    }

    // epilogue: store C to g_hh + fused alpha partial dots
    float ps[4] = {0.f, 0.f, 0.f, 0.f}, pd[4] = {0.f, 0.f, 0.f, 0.f};
#pragma unroll
    for (int mt = 0; mt < 2; mt++) {
        int row0 = warp_m * 32 + mt * 16 + g;
        int row1 = row0 + 8;
#pragma unroll
        for (int nt = 0; nt < 8; nt++) {
            int col = warp_n * 64 + nt * 8 + t * 2;
            float c0 = c[mt][nt][0], c1 = c[mt][nt][1];
            float c2 = c[mt][nt][2], c3 = c[mt][nt][3];
            if (m0 + row0 < NN)
                *(float2*)&g_hh[(m0 + row0) * 512 + h * 128 + col] = make_float2(c0, c1);
            if (m0 + row1 < NN)
                *(float2*)&g_hh[(m0 + row1) * 512 + h * 128 + col] = make_float2(c2, c3);
            float w0 = s_as[col], w1 = s_as[col + 1];
            float d0 = s_ad[col], d1 = s_ad[col + 1];
            ps[mt * 2 + 0] += c0 * w0 + c1 * w1;
            ps[mt * 2 + 1] += c2 * w0 + c3 * w1;
            pd[mt * 2 + 0] += c0 * d0 + c1 * d1;
            pd[mt * 2 + 1] += c2 * d0 + c3 * d1;
        }
    }
#pragma unroll
    for (int off = 1; off <= 2; off <<= 1) {
#pragma unroll
        for (int i = 0; i < 4; i++) {
            ps[i] += __shfl_xor_sync(0xffffffffu, ps[i], off);
            pd[i] += __shfl_xor_sync(0xffffffffu, pd[i], off);
        }
    }
    if (t == 0) {
#pragma unroll
        for (int mt = 0; mt < 2; mt++)
#pragma unroll
            for (int hf = 0; hf < 2; hf++) {
                int row = warp_m * 32 + mt * 16 + hf * 8 + g;
                abuf[0][warp_n][row] = ps[mt * 2 + hf];
                abuf[1][warp_n][row] = pd[mt * 2 + hf];
            }
    }
    __syncthreads();
    if (tid < 128 && m0 + tid < NN) {
        g_as[(m0 + tid) * 4 + h] = abuf[0][0][tid] + abuf[0][1][tid];
        g_ad[(m0 + tid) * 4 + h] = abuf[1][0][tid] + abuf[1][1][tid];
    }
}

// ---------------- GAT aggregation + head-mean + bias + LN + relu + residual ----------------
// 128 threads: two halves process interleaved edges concurrently; each thread owns
// a float2 dim-pair across all 4 heads.
__global__ __launch_bounds__(128) void k_gat(const float* __restrict__ bg,
                                             const float* __restrict__ lnw,
                                             const float* __restrict__ lnb) {
    int node = blockIdx.x, tid = threadIdx.x;
    int h = tid >> 5, lane = tid & 31;
    __shared__ float  sm[4], ss[4], sad[4], rbuf[8];
    __shared__ int    ssrc[32];
    __shared__ float  swt[32][4];
    __shared__ float2 part2[2][4][64];   // [half][head][dim-pair]
    if (tid < 4) sad[tid] = g_ad[node * 4 + tid];
    int beg = g_rowptr[node], end = g_rowptr[node + 1];
    __syncthreads();

    // pass 1: per-head online softmax stats (warp per head)
    float adh = sad[h];
    float m = -1e30f, s = 0.f;
    for (int e = beg + lane; e < end; e += 32) {
        int src = g_esrc[e];
        float x = g_as[src * 4 + h] + adh;
        x = x > 0.f ? x : 0.2f * x;
        float nm = fmaxf(m, x);
        s = s * __expf(m - nm) + __expf(x - nm);
        m = nm;
    }
#pragma unroll
    for (int off = 16; off > 0; off >>= 1) {
        float mo = __shfl_xor_sync(0xffffffffu, m, off);
        float so = __shfl_xor_sync(0xffffffffu, s, off);
        float nm = fmaxf(m, mo);
        s = s * __expf(m - nm) + so * __expf(mo - nm);
        m = nm;
    }
    if (lane == 0) { sm[h] = m; ss[h] = 1.f / s; }
    __syncthreads();

    // pass 2: chunked; halves take interleaved edges, float2 per thread per head
    int half = tid >> 6;     // 0/1
    int t    = tid & 63;     // dim-pair index
    float2 c0 = {0.f, 0.f}, c1 = {0.f, 0.f}, c2 = {0.f, 0.f}, c3 = {0.f, 0.f};
    for (int base = beg; base < end; base += 32) {
        int cnt = end - base; if (cnt > 32) cnt = 32;
        if (tid < cnt * 4) {
            int e  = base + (tid >> 2);
            int hd = tid & 3;
            int src = g_esrc[e];
            float x = g_as[src * 4 + hd] + sad[hd];
            x = x > 0.f ? x : 0.2f * x;
            swt[tid >> 2][hd] = __expf(x - sm[hd]) * ss[hd];
            if (hd == 0) ssrc[tid >> 2] = src;
        }
        __syncthreads();
        for (int j = half; j < cnt; j += 2) {
            int src = ssrc[j];
            float4 w = *(const float4*)swt[j];
            const float2* row = (const float2*)&g_hh[src * 512];
            float2 v0 = row[t], v1 = row[64 + t], v2 = row[128 + t], v3 = row[192 + t];
            c0.x += w.x * v0.x; c0.y += w.x * v0.y;
            c1.x += w.y * v1.x; c1.y += w.y * v1.y;
            c2.x += w.z * v2.x; c2.y += w.z * v2.y;
            c3.x += w.w * v3.x; c3.y += w.w * v3.y;
        }
        __syncthreads();
    }
    part2[half][0][t] = c0;
    part2[half][1][t] = c1;
    part2[half][2][t] = c2;
    part2[half][3][t] = c3;
    __syncthreads();

    // combine halves: thread tid owns dim d = tid
    int td = tid >> 1, cm = tid & 1;
    float o = 0.f;
#pragma unroll
    for (int hh2 = 0; hh2 < 4; hh2++) {
        float2 a = part2[0][hh2][td];
        float2 b = part2[1][hh2][td];
        o += cm ? (a.y + b.y) : (a.x + b.x);
    }
    o = 0.25f * o + bg[tid];

    // layernorm over 128 dims
    float vs = o, vq = o * o;
#pragma unroll
    for (int off = 16; off > 0; off >>= 1) {
        vs += __shfl_xor_sync(0xffffffffu, vs, off);
        vq += __shfl_xor_sync(0xffffffffu, vq, off);
    }
    if (lane == 0) { rbuf[h] = vs; rbuf[4 + h] = vq; }
    __syncthreads();
    float tot  = rbuf[0] + rbuf[1] + rbuf[2] + rbuf[3];
    float tot2 = rbuf[4] + rbuf[5] + rbuf[6] + rbuf[7];
    float mu  = tot * (1.f / 128.f);
    float var = tot2 * (1.f / 128.f) - mu * mu;
    float val = (o - mu) * rsqrtf(var + 1e-5f) * lnw[tid] + lnb[tid];
    g_h[node * DH + tid] += fmaxf(val, 0.f);
}

// ---------------- pooling (batch is sorted -> contiguous segments) ----------------
__global__ void k_pool() {
    int g = blockIdx.x, d = threadIdx.x;
    int beg = g_gstart[g], end = g_gstart[g + 1];
    float s = 0.f, mx = -1e30f;
    for (int i = beg; i < end; i++) {
        float v = g_h[i * DH + d];
        s += v;
        mx = fmaxf(mx, v);
    }
    int cnt = end - beg;
    float denom = (float)(cnt > 0 ? cnt : 1);
    g_pool[g * 320 + d]       = s / denom;
    g_pool[g * 320 + 128 + d] = (cnt > 0) ? mx : 0.f;
}

// ---------------- trunk + task heads (TDA branch fused in) ----------------
__global__ __launch_bounds__(256) void k_head(const float* __restrict__ tda,
                                              const float* __restrict__ wt1, const float* __restrict__ bt1,
                                              const float* __restrict__ wt2, const float* __restrict__ bt2,
                                              const float* __restrict__ wsh1, const float* __restrict__ bsh1,
                                              const float* __restrict__ wsh2, const float* __restrict__ bsh2,
                                              const float* __restrict__ wh1,  const float* __restrict__ bh1,
                                              const float* __restrict__ wh2,  const float* __restrict__ bh2,
                                              float* __restrict__ out) {
    int g = blockIdx.x, tid = threadIdx.x;
    __shared__ float comb[320], s1[256], s2[128], hh1[NT * 64], th1[64];
    for (int i = tid; i < 256; i += 256) comb[i] = g_pool[g * 320 + i];
    __syncthreads();
    // TDA branch on threads 0..63
    if (tid < 64) {
        float a = bt1[tid];
#pragma unroll
        for (int k = 0; k < FT; k++) a += tda[g * FT + k] * wt1[k * 64 + tid];
        th1[tid] = fmaxf(a, 0.f);
    }
    __syncthreads();
    if (tid < 64) {
        float c = bt2[tid];
#pragma unroll
        for (int k = 0; k < 64; k++) c += th1[k] * wt2[k * 64 + tid];
        comb[256 + tid] = fmaxf(c, 0.f);
    }
    __syncthreads();
    float a = bsh1[tid];
    for (int k = 0; k < 320; k++) a += comb[k] * wsh1[k * 256 + tid];
    s1[tid] = fmaxf(a, 0.f);
    __syncthreads();
    if (tid < 128) {
        float c = bsh2[tid];
        for (int k = 0; k < 256; k++) c += s1[k] * wsh2[k * 128 + tid];
        s2[tid] = fmaxf(c, 0.f);
    }
    __syncthreads();
    for (int idx = tid; idx < NT * 64; idx += 256) {
        int t = idx >> 6, kk = idx & 63;
        float c = bh1[t * 64 + kk];
        for (int k = 0; k < 128; k++) c += s2[k] * wh1[t * 8192 + k * 64 + kk];
        hh1[idx] = fmaxf(c, 0.f);
    }
    __syncthreads();
    if (tid < NT) {
        float c = bh2[tid];
        for (int k = 0; k < 64; k++) c += hh1[tid * 64 + k] * wh2[tid * 64 + k];
        out[tid * NGR + g] = c;
    }
}

// ---------------- launch ----------------
extern "C" void kernel_launch(void* const* d_in, const int* in_sizes, int n_in,
                              void* d_out, int out_size) {
    const float* x       = (const float*)d_in[0];
    const int*   ei      = (const int*)d_in[1];
    const int*   batch   = (const int*)d_in[2];
    const float* tda     = (const float*)d_in[3];
    const float* w_in    = (const float*)d_in[4];
    const float* b_in    = (const float*)d_in[5];
    const float* w_gat   = (const float*)d_in[6];
    const float* a_src   = (const float*)d_in[7];
    const float* a_dst   = (const float*)d_in[8];
    const float* b_gat   = (const float*)d_in[9];
    const float* ln_w    = (const float*)d_in[10];
    const float* ln_b    = (const float*)d_in[11];
    const float* w_tda1  = (const float*)d_in[12];
    const float* b_tda1  = (const float*)d_in[13];
    const float* w_tda2  = (const float*)d_in[14];
    const float* b_tda2  = (const float*)d_in[15];
    const float* w_sh1   = (const float*)d_in[16];
    const float* b_sh1   = (const float*)d_in[17];
    const float* w_sh2   = (const float*)d_in[18];
    const float* b_sh2   = (const float*)d_in[19];
    const float* w_h1    = (const float*)d_in[20];
    const float* b_h1    = (const float*)d_in[21];
    const float* w_h2    = (const float*)d_in[22];
    const float* b_h2    = (const float*)d_in[23];
    float* out = (float*)d_out;

    // order chosen so the ncu-profiled slot lands on k_gemm_tc (layer 0)
    k_inproj<<<NN, 128>>>(x, w_in, b_in);                      // 0
    k_prep<<<(NN + 256) / 256, 256>>>(batch);                  // 1
    k_count<<<(ETOT + 255) / 256, 256>>>(ei);                  // 2
    k_gemm_tc<<<dim3((NN + 127) / 128, 4), 256>>>(w_gat,       // 3  (layer 0 GEMM)
                                                  a_src, a_dst);
    k_scan<<<1, 1024>>>();                                     // 4
    k_scatter<<<(ETOT + 255) / 256, 256>>>(ei);                // 5
    k_gat<<<NN, 128>>>(b_gat, ln_w, ln_b);                     // 6  (layer 0 agg)

    for (int l = 1; l < NL; l++) {
        k_gemm_tc<<<dim3((NN + 127) / 128, 4), 256>>>(w_gat + l * 128 * 512,
                                                      a_src + l * 512, a_dst + l * 512);
        k_gat<<<NN, 128>>>(b_gat + l * 128, ln_w + l * 128, ln_b + l * 128);
    }

    // pooling + fused TDA/trunk/heads
    k_pool<<<NGR, 128>>>();
    k_head<<<NGR, 256>>>(tda, w_tda1, b_tda1, w_tda2, b_tda2,
                         w_sh1, b_sh1, w_sh2, b_sh2, w_h1, b_h1, w_h2, b_h2, out);
}

// round 6
// speedup vs baseline: 1.2008x; 1.2008x over previous
#include <cuda_runtime.h>
#include <cuda_bf16.h>
#include <math.h>

#define NN   20000        // nodes
#define NE   320000       // edges (without self loops)
#define ETOT (NE + NN)    // edges + self loops
#define NGR  256          // graphs
#define FD   11           // node feature dim
#define FT   30           // tda feature dim
#define DH   128          // hidden
#define NH   4            // heads
#define NL   3            // layers
#define NT   6            // tasks

#define APAD 40           // A smem row length (32 k + 8 pad) in bf16
#define BPAD 136          // B smem row length (128 n + 8 pad) in bf16

// ---------------- device scratch (static, no allocations) ----------------
// Referenced ONLY inside kernels — never passed as kernel arguments.
__device__ float  g_h[NN * DH];            // node features (in-place updated)
__device__ float  g_hh[NN * NH * DH];      // per-head transformed features [N,512]
__device__ float  g_as[NN * NH];           // alpha_src per node/head
__device__ float  g_ad[NN * NH];           // alpha_dst per node/head
__device__ int    g_rowptr[NN + 1];
__device__ int    g_cnt[NN];               // counts, then scatter cursor
__device__ int    g_esrc[ETOT];            // src ids sorted by dst
__device__ int    g_gstart[NGR + 1];
__device__ float  g_pool[NGR * 320];       // [mean(128) | max(128) | tda(64)]

// ---------------- bf16 mma helpers ----------------
__device__ __forceinline__ void mma_bf16(float c[4], const unsigned a[4], const unsigned* b) {
    asm volatile(
        "mma.sync.aligned.m16n8k16.row.col.f32.bf16.bf16.f32 "
        "{%0,%1,%2,%3}, {%4,%5,%6,%7}, {%8,%9}, {%0,%1,%2,%3};\n"
        : "+f"(c[0]), "+f"(c[1]), "+f"(c[2]), "+f"(c[3])
        : "r"(a[0]), "r"(a[1]), "r"(a[2]), "r"(a[3]), "r"(b[0]), "r"(b[1]));
}

__device__ __forceinline__ void ldsm_x4(unsigned r[4], unsigned saddr) {
    asm volatile("ldmatrix.sync.aligned.m8n8.x4.shared.b16 {%0,%1,%2,%3}, [%4];"
        : "=r"(r[0]), "=r"(r[1]), "=r"(r[2]), "=r"(r[3]) : "r"(saddr));
}

__device__ __forceinline__ void ldsm_x4_t(unsigned r[4], unsigned saddr) {
    asm volatile("ldmatrix.sync.aligned.m8n8.x4.trans.shared.b16 {%0,%1,%2,%3}, [%4];"
        : "=r"(r[0]), "=r"(r[1]), "=r"(r[2]), "=r"(r[3]) : "r"(saddr));
}

__device__ __forceinline__ void split2(float x, float y, __nv_bfloat162& hi, __nv_bfloat162& lo) {
    __nv_bfloat16 hx = __float2bfloat16_rn(x), hy = __float2bfloat16_rn(y);
    __nv_bfloat16 lx = __float2bfloat16_rn(x - __bfloat162float(hx));
    __nv_bfloat16 ly = __float2bfloat16_rn(y - __bfloat162float(hy));
    hi.x = hx; hi.y = hy;
    lo.x = lx; lo.y = ly;
}

// ---------------- CSR build ----------------
__global__ void k_prep(const int* __restrict__ batch) {
    int i = blockIdx.x * blockDim.x + threadIdx.x;
    if (i < NN) g_cnt[i] = 0;
    if (i <= NN) {
        int b  = (i < NN) ? batch[i] : NGR;
        int bp = (i > 0) ? batch[i - 1] : -1;
        for (int g = bp + 1; g <= b && g <= NGR; g++) g_gstart[g] = i;
    }
}

__global__ void k_count(const int* __restrict__ ei) {
    int i = blockIdx.x * blockDim.x + threadIdx.x;
    if (i >= ETOT) return;
    int dst = (i < NE) ? ei[NE + i] : (i - NE);
    atomicAdd(&g_cnt[dst], 1);
}

__global__ void k_scan() {   // single block, 1024 threads, chunk=20; also writes cursor
    __shared__ int ssum[1024];
    const int CH = 20;
    int tid = threadIdx.x;
    int base = tid * CH;
    int s = 0;
    for (int j = 0; j < CH; j++) {
        int idx = base + j;
        if (idx < NN) s += g_cnt[idx];
    }
    ssum[tid] = s;
    __syncthreads();
    for (int off = 1; off < 1024; off <<= 1) {
        int v = 0;
        if (tid >= off) v = ssum[tid - off];
        __syncthreads();
        ssum[tid] += v;
        __syncthreads();
    }
    int run = tid ? ssum[tid - 1] : 0;
    for (int j = 0; j < CH; j++) {
        int idx = base + j;
        if (idx < NN) {
            int c = g_cnt[idx];
            g_rowptr[idx] = run;
            g_cnt[idx]    = run;   // scatter cursor
            run += c;
        }
    }
    if (tid == 1023) g_rowptr[NN] = ssum[1023];
}

__global__ void k_scatter(const int* __restrict__ ei) {
    int i = blockIdx.x * blockDim.x + threadIdx.x;
    if (i >= ETOT) return;
    int src, dst;
    if (i < NE) { src = ei[i]; dst = ei[NE + i]; }
    else        { src = i - NE; dst = i - NE; }
    int pos = atomicAdd(&g_cnt[dst], 1);
    g_esrc[pos] = src;
}

// ---------------- input projection: h = relu(x @ w_in + b_in) ----------------
__global__ void k_inproj(const float* __restrict__ x, const float* __restrict__ w,
                         const float* __restrict__ b) {
    int n = blockIdx.x, d = threadIdx.x;
    __shared__ float xs[FD];
    if (d < FD) xs[d] = x[n * FD + d];
    __syncthreads();
    float a = b[d];
#pragma unroll
    for (int k = 0; k < FD; k++) a += xs[k] * w[k * DH + d];
    g_h[n * DH + d] = fmaxf(a, 0.f);
}

// ---------------- bf16 split tensor-core GEMM + fused alpha dots ----------------
// block: 128 rows x one head (128 cols). grid (157, 4). 256 threads = 8 warps (4m x 2n).
__global__ __launch_bounds__(256) void k_gemm_tc(const float* __restrict__ B,
                                                 const float* __restrict__ aw_s,
                                                 const float* __restrict__ aw_d) {
    __shared__ alignas(16) __nv_bfloat16 As_h[128][APAD], As_l[128][APAD];   // [m][k]
    __shared__ alignas(16) __nv_bfloat16 Bs_h[32][BPAD],  Bs_l[32][BPAD];    // [k][n]
    __shared__ float s_as[128], s_ad[128];
    __shared__ float abuf[2][2][128];   // [s/d][warp_n][row]

    int tid = threadIdx.x;
    int wid = tid >> 5, lane = tid & 31;
    int warp_m = wid & 3, warp_n = wid >> 2;
    int m0 = blockIdx.x * 128;
    int h  = blockIdx.y;
    int g  = lane >> 2, t = lane & 3;

    if (tid < 128) { s_as[tid] = aw_s[h * 128 + tid]; s_ad[tid] = aw_d[h * 128 + tid]; }

    float c[2][8][4];
#pragma unroll
    for (int mt = 0; mt < 2; mt++)
#pragma unroll
        for (int nt = 0; nt < 8; nt++)
#pragma unroll
            for (int i = 0; i < 4; i++) c[mt][nt][i] = 0.f;

    // tile-load thread mapping
    int ar  = tid >> 1, akg = (tid & 1) * 16;    // A: 16 k-floats per thread
    int bkr = tid >> 3, bcg = (tid & 7) * 16;    // B: 16 n-floats per thread

    // ldmatrix per-lane address offsets
    int lrow = (lane & 7) + ((lane >> 3) & 1) * 8;   // row within 16-row tile
    int lcol = (lane >> 4) * 8;                      // k(8) or n(8) sub-offset
    unsigned sAh = (unsigned)__cvta_generic_to_shared(As_h);
    unsigned sAl = (unsigned)__cvta_generic_to_shared(As_l);
    unsigned sBh = (unsigned)__cvta_generic_to_shared(Bs_h);
    unsigned sBl = (unsigned)__cvta_generic_to_shared(Bs_l);

    for (int kc = 0; kc < 128; kc += 32) {
        __syncthreads();
        // load + split A tile [128 x 32]
        {
            bool ok = (m0 + ar < NN);
#pragma unroll
            for (int j = 0; j < 4; j++) {
                float4 v = make_float4(0.f, 0.f, 0.f, 0.f);
                if (ok) v = *(const float4*)&g_h[(m0 + ar) * 128 + kc + akg + j * 4];
                __nv_bfloat162 h0, l0, h1, l1;
                split2(v.x, v.y, h0, l0);
                split2(v.z, v.w, h1, l1);
                *(__nv_bfloat162*)&As_h[ar][akg + j * 4]     = h0;
                *(__nv_bfloat162*)&As_h[ar][akg + j * 4 + 2] = h1;
                *(__nv_bfloat162*)&As_l[ar][akg + j * 4]     = l0;
                *(__nv_bfloat162*)&As_l[ar][akg + j * 4 + 2] = l1;
            }
        }
        // load + split B tile [32 x 128] (k-major, n contiguous)
#pragma unroll
        for (int j = 0; j < 4; j++) {
            float4 v = *(const float4*)&B[(kc + bkr) * 512 + h * 128 + bcg + j * 4];
            __nv_bfloat162 h0, l0, h1, l1;
            split2(v.x, v.y, h0, l0);
            split2(v.z, v.w, h1, l1);
            *(__nv_bfloat162*)&Bs_h[bkr][bcg + j * 4]     = h0;
            *(__nv_bfloat162*)&Bs_h[bkr][bcg + j * 4 + 2] = h1;
            *(__nv_bfloat162*)&Bs_l[bkr][bcg + j * 4]     = l0;
            *(__nv_bfloat162*)&Bs_l[bkr][bcg + j * 4 + 2] = l1;
        }
        __syncthreads();

#pragma unroll
        for (int kk = 0; kk < 32; kk += 16) {
            unsigned ah[2][4], al[2][4];
#pragma unroll
            for (int mt = 0; mt < 2; mt++) {
                unsigned off = (unsigned)(((warp_m * 32 + mt * 16 + lrow) * APAD + kk + lcol) * 2);
                ldsm_x4(ah[mt], sAh + off);
                ldsm_x4(al[mt], sAl + off);
            }
#pragma unroll
            for (int p = 0; p < 4; p++) {           // pairs of n-tiles
                unsigned boff = (unsigned)(((kk + lrow) * BPAD + warp_n * 64 + p * 16 + lcol) * 2);
                unsigned bh[4], bl[4];
                ldsm_x4_t(bh, sBh + boff);
                ldsm_x4_t(bl, sBl + boff);
#pragma unroll
                for (int q = 0; q < 2; q++) {       // sub n-tile (8 cols each)
#pragma unroll
                    for (int mt = 0; mt < 2; mt++) {
                        float* cc = c[mt][p * 2 + q];
                        mma_bf16(cc, ah[mt], &bh[q * 2]);
                        mma_bf16(cc, ah[mt], &bl[q * 2]);
                        mma_bf16(cc, al[mt], &bh[q * 2]);
                    }
                }
            }
        }
    }

    // epilogue: store C to g_hh + fused alpha partial dots
    float ps[4] = {0.f, 0.f, 0.f, 0.f}, pd[4] = {0.f, 0.f, 0.f, 0.f};
#pragma unroll
    for (int mt = 0; mt < 2; mt++) {
        int row0 = warp_m * 32 + mt * 16 + g;
        int row1 = row0 + 8;
#pragma unroll
        for (int nt = 0; nt < 8; nt++) {
            int col = warp_n * 64 + nt * 8 + t * 2;
            float c0 = c[mt][nt][0], c1 = c[mt][nt][1];
            float c2 = c[mt][nt][2], c3 = c[mt][nt][3];
            if (m0 + row0 < NN)
                *(float2*)&g_hh[(m0 + row0) * 512 + h * 128 + col] = make_float2(c0, c1);
            if (m0 + row1 < NN)
                *(float2*)&g_hh[(m0 + row1) * 512 + h * 128 + col] = make_float2(c2, c3);
            float w0 = s_as[col], w1 = s_as[col + 1];
            float d0 = s_ad[col], d1 = s_ad[col + 1];
            ps[mt * 2 + 0] += c0 * w0 + c1 * w1;
            ps[mt * 2 + 1] += c2 * w0 + c3 * w1;
            pd[mt * 2 + 0] += c0 * d0 + c1 * d1;
            pd[mt * 2 + 1] += c2 * d0 + c3 * d1;
        }
    }
#pragma unroll
    for (int off = 1; off <= 2; off <<= 1) {
#pragma unroll
        for (int i = 0; i < 4; i++) {
            ps[i] += __shfl_xor_sync(0xffffffffu, ps[i], off);
            pd[i] += __shfl_xor_sync(0xffffffffu, pd[i], off);
        }
    }
    if (t == 0) {
#pragma unroll
        for (int mt = 0; mt < 2; mt++)
#pragma unroll
            for (int hf = 0; hf < 2; hf++) {
                int row = warp_m * 32 + mt * 16 + hf * 8 + g;
                abuf[0][warp_n][row] = ps[mt * 2 + hf];
                abuf[1][warp_n][row] = pd[mt * 2 + hf];
            }
    }
    __syncthreads();
    if (tid < 128 && m0 + tid < NN) {
        g_as[(m0 + tid) * 4 + h] = abuf[0][0][tid] + abuf[0][1][tid];
        g_ad[(m0 + tid) * 4 + h] = abuf[1][0][tid] + abuf[1][1][tid];
    }
}

// ---------------- GAT aggregation + head-mean + bias + LN + relu + residual ----------------
__global__ __launch_bounds__(128) void k_gat(const float* __restrict__ bg,
                                             const float* __restrict__ lnw,
                                             const float* __restrict__ lnb) {
    int node = blockIdx.x, tid = threadIdx.x;
    int h = tid >> 5, lane = tid & 31;
    __shared__ float sm[4], ss[4], sad[4], rbuf[8];
    __shared__ int   ssrc[32];
    __shared__ float swt[32][4];
    if (tid < 4) sad[tid] = g_ad[node * 4 + tid];
    int beg = g_rowptr[node], end = g_rowptr[node + 1];
    __syncthreads();

    // pass 1: per-head online softmax stats (warp per head)
    float adh = sad[h];
    float m = -1e30f, s = 0.f;
    for (int e = beg + lane; e < end; e += 32) {
        int src = g_esrc[e];
        float x = g_as[src * 4 + h] + adh;
        x = x > 0.f ? x : 0.2f * x;
        float nm = fmaxf(m, x);
        s = s * __expf(m - nm) + __expf(x - nm);
        m = nm;
    }
#pragma unroll
    for (int off = 16; off > 0; off >>= 1) {
        float mo = __shfl_xor_sync(0xffffffffu, m, off);
        float so = __shfl_xor_sync(0xffffffffu, s, off);
        float nm = fmaxf(m, mo);
        s = s * __expf(m - nm) + so * __expf(mo - nm);
        m = nm;
    }
    if (lane == 0) { sm[h] = m; ss[h] = 1.f / s; }
    __syncthreads();

    // pass 2: chunked — compute each edge/head weight exactly once
    float c0 = 0.f, c1 = 0.f, c2 = 0.f, c3 = 0.f;
    for (int base = beg; base < end; base += 32) {
        int cnt = end - base; if (cnt > 32) cnt = 32;
        if (tid < cnt * 4) {
            int e  = base + (tid >> 2);
            int hd = tid & 3;
            int src = g_esrc[e];
            float x = g_as[src * 4 + hd] + sad[hd];
            x = x > 0.f ? x : 0.2f * x;
            swt[tid >> 2][hd] = __expf(x - sm[hd]) * ss[hd];
            if (hd == 0) ssrc[tid >> 2] = src;
        }
        __syncthreads();
        for (int j = 0; j < cnt; j++) {
            int src = ssrc[j];
            float4 w = *(const float4*)swt[j];
            const float* row = &g_hh[src * 512];
            c0 += w.x * row[tid];
            c1 += w.y * row[128 + tid];
            c2 += w.z * row[256 + tid];
            c3 += w.w * row[384 + tid];
        }
        __syncthreads();
    }
    float o = 0.25f * (c0 + c1 + c2 + c3) + bg[tid];

    // layernorm over 128 dims
    float vs = o, vq = o * o;
#pragma unroll
    for (int off = 16; off > 0; off >>= 1) {
        vs += __shfl_xor_sync(0xffffffffu, vs, off);
        vq += __shfl_xor_sync(0xffffffffu, vq, off);
    }
    if (lane == 0) { rbuf[h] = vs; rbuf[4 + h] = vq; }
    __syncthreads();
    float tot  = rbuf[0] + rbuf[1] + rbuf[2] + rbuf[3];
    float tot2 = rbuf[4] + rbuf[5] + rbuf[6] + rbuf[7];
    float mu  = tot * (1.f / 128.f);
    float var = tot2 * (1.f / 128.f) - mu * mu;
    float val = (o - mu) * rsqrtf(var + 1e-5f) * lnw[tid] + lnb[tid];
    g_h[node * DH + tid] += fmaxf(val, 0.f);
}

// ---------------- pooling (batch is sorted -> contiguous segments) ----------------
__global__ void k_pool() {
    int g = blockIdx.x, d = threadIdx.x;
    int beg = g_gstart[g], end = g_gstart[g + 1];
    float s = 0.f, mx = -1e30f;
    for (int i = beg; i < end; i++) {
        float v = g_h[i * DH + d];
        s += v;
        mx = fmaxf(mx, v);
    }
    int cnt = end - beg;
    float denom = (float)(cnt > 0 ? cnt : 1);
    g_pool[g * 320 + d]       = s / denom;
    g_pool[g * 320 + 128 + d] = (cnt > 0) ? mx : 0.f;
}

// ---------------- trunk + task heads (TDA branch fused in) ----------------
__global__ __launch_bounds__(256) void k_head(const float* __restrict__ tda,
                                              const float* __restrict__ wt1, const float* __restrict__ bt1,
                                              const float* __restrict__ wt2, const float* __restrict__ bt2,
                                              const float* __restrict__ wsh1, const float* __restrict__ bsh1,
                                              const float* __restrict__ wsh2, const float* __restrict__ bsh2,
                                              const float* __restrict__ wh1,  const float* __restrict__ bh1,
                                              const float* __restrict__ wh2,  const float* __restrict__ bh2,
                                              float* __restrict__ out) {
    int g = blockIdx.x, tid = threadIdx.x;
    __shared__ float comb[320], s1[256], s2[128], hh1[NT * 64], th1[64];
    for (int i = tid; i < 256; i += 256) comb[i] = g_pool[g * 320 + i];
    __syncthreads();
    if (tid < 64) {
        float a = bt1[tid];
#pragma unroll
        for (int k = 0; k < FT; k++) a += tda[g * FT + k] * wt1[k * 64 + tid];
        th1[tid] = fmaxf(a, 0.f);
    }
    __syncthreads();
    if (tid < 64) {
        float c = bt2[tid];
#pragma unroll
        for (int k = 0; k < 64; k++) c += th1[k] * wt2[k * 64 + tid];
        comb[256 + tid] = fmaxf(c, 0.f);
    }
    __syncthreads();
    float a = bsh1[tid];
    for (int k = 0; k < 320; k++) a += comb[k] * wsh1[k * 256 + tid];
    s1[tid] = fmaxf(a, 0.f);
    __syncthreads();
    if (tid < 128) {
        float c = bsh2[tid];
        for (int k = 0; k < 256; k++) c += s1[k] * wsh2[k * 128 + tid];
        s2[tid] = fmaxf(c, 0.f);
    }
    __syncthreads();
    for (int idx = tid; idx < NT * 64; idx += 256) {
        int t = idx >> 6, kk = idx & 63;
        float c = bh1[t * 64 + kk];
        for (int k = 0; k < 128; k++) c += s2[k] * wh1[t * 8192 + k * 64 + kk];
        hh1[idx] = fmaxf(c, 0.f);
    }
    __syncthreads();
    if (tid < NT) {
        float c = bh2[tid];
        for (int k = 0; k < 64; k++) c += hh1[tid * 64 + k] * wh2[tid * 64 + k];
        out[tid * NGR + g] = c;
    }
}

// ---------------- launch ----------------
extern "C" void kernel_launch(void* const* d_in, const int* in_sizes, int n_in,
                              void* d_out, int out_size) {
    const float* x       = (const float*)d_in[0];
    const int*   ei      = (const int*)d_in[1];
    const int*   batch   = (const int*)d_in[2];
    const float* tda     = (const float*)d_in[3];
    const float* w_in    = (const float*)d_in[4];
    const float* b_in    = (const float*)d_in[5];
    const float* w_gat   = (const float*)d_in[6];
    const float* a_src   = (const float*)d_in[7];
    const float* a_dst   = (const float*)d_in[8];
    const float* b_gat   = (const float*)d_in[9];
    const float* ln_w    = (const float*)d_in[10];
    const float* ln_b    = (const float*)d_in[11];
    const float* w_tda1  = (const float*)d_in[12];
    const float* b_tda1  = (const float*)d_in[13];
    const float* w_tda2  = (const float*)d_in[14];
    const float* b_tda2  = (const float*)d_in[15];
    const float* w_sh1   = (const float*)d_in[16];
    const float* b_sh1   = (const float*)d_in[17];
    const float* w_sh2   = (const float*)d_in[18];
    const float* b_sh2   = (const float*)d_in[19];
    const float* w_h1    = (const float*)d_in[20];
    const float* b_h1    = (const float*)d_in[21];
    const float* w_h2    = (const float*)d_in[22];
    const float* b_h2    = (const float*)d_in[23];
    float* out = (float*)d_out;

    // order chosen so the ncu-profiled slot lands on k_gemm_tc (layer 0)
    k_inproj<<<NN, 128>>>(x, w_in, b_in);                      // 0
    k_prep<<<(NN + 256) / 256, 256>>>(batch);                  // 1
    k_count<<<(ETOT + 255) / 256, 256>>>(ei);                  // 2
    k_gemm_tc<<<dim3((NN + 127) / 128, 4), 256>>>(w_gat,       // 3  (layer 0 GEMM)
                                                  a_src, a_dst);
    k_scan<<<1, 1024>>>();                                     // 4
    k_scatter<<<(ETOT + 255) / 256, 256>>>(ei);                // 5
    k_gat<<<NN, 128>>>(b_gat, ln_w, ln_b);                     // 6  (layer 0 agg)

    for (int l = 1; l < NL; l++) {
        k_gemm_tc<<<dim3((NN + 127) / 128, 4), 256>>>(w_gat + l * 128 * 512,
                                                      a_src + l * 512, a_dst + l * 512);
        k_gat<<<NN, 128>>>(b_gat + l * 128, ln_w + l * 128, ln_b + l * 128);
    }

    // pooling + fused TDA/trunk/heads
    k_pool<<<NGR, 128>>>();
    k_head<<<NGR, 256>>>(tda, w_tda1, b_tda1, w_tda2, b_tda2,
                         w_sh1, b_sh1, w_sh2, b_sh2, w_h1, b_h1, w_h2, b_h2, out);
}

// round 7
// speedup vs baseline: 1.2403x; 1.0329x over previous
#include <cuda_runtime.h>
#include <cuda_bf16.h>
#include <math.h>

#define NN   20000        // nodes
#define NE   320000       // edges (without self loops)
#define ETOT (NE + NN)    // edges + self loops
#define NGR  256          // graphs
#define FD   11           // node feature dim
#define FT   30           // tda feature dim
#define DH   128          // hidden
#define NH   4            // heads
#define NL   3            // layers
#define NT   6            // tasks

#define APAD 40           // A smem row length (32 k + 8 pad) in bf16
#define BPAD 136          // B smem row length (128 n + 8 pad) in bf16

// ---------------- device scratch (static, no allocations) ----------------
// Referenced ONLY inside kernels — never passed as kernel arguments.
__device__ float         g_h[NN * DH];          // node features (in-place updated)
__device__ __nv_bfloat16 g_ah[NN * DH];         // bf16 hi of g_h
__device__ __nv_bfloat16 g_al[NN * DH];         // bf16 lo of g_h
__device__ __nv_bfloat16 g_w_hi[NL * DH * NH * DH];  // bf16 hi of w_gat
__device__ __nv_bfloat16 g_w_lo[NL * DH * NH * DH];  // bf16 lo of w_gat
__device__ float         g_hh[NN * NH * DH];    // per-head transformed features [N,512]
__device__ float         g_as[NN * NH];         // alpha_src per node/head
__device__ float         g_ad[NN * NH];         // alpha_dst per node/head
__device__ int           g_rowptr[NN + 1];
__device__ int           g_cnt[NN];             // counts, then scatter cursor
__device__ int           g_esrc[ETOT];          // src ids sorted by dst
__device__ int           g_gstart[NGR + 1];
__device__ float         g_pool[NGR * 320];     // [mean(128) | max(128) | tda(64)]

// ---------------- bf16 mma helpers ----------------
__device__ __forceinline__ void mma_bf16(float c[4], const unsigned a[4], const unsigned* b) {
    asm volatile(
        "mma.sync.aligned.m16n8k16.row.col.f32.bf16.bf16.f32 "
        "{%0,%1,%2,%3}, {%4,%5,%6,%7}, {%8,%9}, {%0,%1,%2,%3};\n"
        : "+f"(c[0]), "+f"(c[1]), "+f"(c[2]), "+f"(c[3])
        : "r"(a[0]), "r"(a[1]), "r"(a[2]), "r"(a[3]), "r"(b[0]), "r"(b[1]));
}

__device__ __forceinline__ void ldsm_x4(unsigned r[4], unsigned saddr) {
    asm volatile("ldmatrix.sync.aligned.m8n8.x4.shared.b16 {%0,%1,%2,%3}, [%4];"
        : "=r"(r[0]), "=r"(r[1]), "=r"(r[2]), "=r"(r[3]) : "r"(saddr));
}

__device__ __forceinline__ void ldsm_x4_t(unsigned r[4], unsigned saddr) {
    asm volatile("ldmatrix.sync.aligned.m8n8.x4.trans.shared.b16 {%0,%1,%2,%3}, [%4];"
        : "=r"(r[0]), "=r"(r[1]), "=r"(r[2]), "=r"(r[3]) : "r"(saddr));
}

// ---------------- weight split (all layers) ----------------
__global__ void k_wsplit(const float* __restrict__ w) {
    int i = blockIdx.x * blockDim.x + threadIdx.x;
    if (i >= NL * DH * NH * DH) return;
    float v = w[i];
    __nv_bfloat16 hi = __float2bfloat16_rn(v);
    g_w_hi[i] = hi;
    g_w_lo[i] = __float2bfloat16_rn(v - __bfloat162float(hi));
}

// ---------------- CSR build ----------------
__global__ void k_prep(const int* __restrict__ batch) {
    int i = blockIdx.x * blockDim.x + threadIdx.x;
    if (i < NN) g_cnt[i] = 0;
    if (i <= NN) {
        int b  = (i < NN) ? batch[i] : NGR;
        int bp = (i > 0) ? batch[i - 1] : -1;
        for (int g = bp + 1; g <= b && g <= NGR; g++) g_gstart[g] = i;
    }
}

__global__ void k_count(const int* __restrict__ ei) {
    int i = blockIdx.x * blockDim.x + threadIdx.x;
    if (i >= ETOT) return;
    int dst = (i < NE) ? ei[NE + i] : (i - NE);
    atomicAdd(&g_cnt[dst], 1);
}

__global__ void k_scan() {   // single block, 1024 threads, chunk=20; also writes cursor
    __shared__ int ssum[1024];
    const int CH = 20;
    int tid = threadIdx.x;
    int base = tid * CH;
    int s = 0;
    for (int j = 0; j < CH; j++) {
        int idx = base + j;
        if (idx < NN) s += g_cnt[idx];
    }
    ssum[tid] = s;
    __syncthreads();
    for (int off = 1; off < 1024; off <<= 1) {
        int v = 0;
        if (tid >= off) v = ssum[tid - off];
        __syncthreads();
        ssum[tid] += v;
        __syncthreads();
    }
    int run = tid ? ssum[tid - 1] : 0;
    for (int j = 0; j < CH; j++) {
        int idx = base + j;
        if (idx < NN) {
            int c = g_cnt[idx];
            g_rowptr[idx] = run;
            g_cnt[idx]    = run;   // scatter cursor
            run += c;
        }
    }
    if (tid == 1023) g_rowptr[NN] = ssum[1023];
}

__global__ void k_scatter(const int* __restrict__ ei) {
    int i = blockIdx.x * blockDim.x + threadIdx.x;
    if (i >= ETOT) return;
    int src, dst;
    if (i < NE) { src = ei[i]; dst = ei[NE + i]; }
    else        { src = i - NE; dst = i - NE; }
    int pos = atomicAdd(&g_cnt[dst], 1);
    g_esrc[pos] = src;
}

// ---------------- input projection: h = relu(x @ w_in + b_in), + bf16 split ----------------
__global__ void k_inproj(const float* __restrict__ x, const float* __restrict__ w,
                         const float* __restrict__ b) {
    int n = blockIdx.x, d = threadIdx.x;
    __shared__ float xs[FD];
    if (d < FD) xs[d] = x[n * FD + d];
    __syncthreads();
    float a = b[d];
#pragma unroll
    for (int k = 0; k < FD; k++) a += xs[k] * w[k * DH + d];
    float v = fmaxf(a, 0.f);
    g_h[n * DH + d] = v;
    __nv_bfloat16 hi = __float2bfloat16_rn(v);
    g_ah[n * DH + d] = hi;
    g_al[n * DH + d] = __float2bfloat16_rn(v - __bfloat162float(hi));
}

// ---------------- bf16 split tensor-core GEMM + fused alpha dots ----------------
// block: 128 rows x one head (128 cols). grid (157, 4). 256 threads = 8 warps (4m x 2n).
__global__ __launch_bounds__(256, 2) void k_gemm_tc(int layer,
                                                    const float* __restrict__ aw_s,
                                                    const float* __restrict__ aw_d) {
    __shared__ alignas(16) __nv_bfloat16 As_h[128][APAD], As_l[128][APAD];   // [m][k]
    __shared__ alignas(16) __nv_bfloat16 Bs_h[32][BPAD],  Bs_l[32][BPAD];    // [k][n]
    __shared__ float s_as[128], s_ad[128];
    __shared__ float abuf[2][2][128];   // [s/d][warp_n][row]

    int tid = threadIdx.x;
    int wid = tid >> 5, lane = tid & 31;
    int warp_m = wid & 3, warp_n = wid >> 2;
    int m0 = blockIdx.x * 128;
    int h  = blockIdx.y;
    int g  = lane >> 2, t = lane & 3;
    const __nv_bfloat16* Bh = g_w_hi + layer * DH * NH * DH;
    const __nv_bfloat16* Bl = g_w_lo + layer * DH * NH * DH;

    if (tid < 128) { s_as[tid] = aw_s[h * 128 + tid]; s_ad[tid] = aw_d[h * 128 + tid]; }

    float c[2][8][4];
#pragma unroll
    for (int mt = 0; mt < 2; mt++)
#pragma unroll
        for (int nt = 0; nt < 8; nt++)
#pragma unroll
            for (int i = 0; i < 4; i++) c[mt][nt][i] = 0.f;

    // tile-load thread mapping (16 bf16 = 2 uint4 per thread per array)
    int ar  = tid >> 1, akg = (tid & 1) * 16;    // A
    int bkr = tid >> 3, bcg = (tid & 7) * 16;    // B

    // ldmatrix per-lane address offsets
    int lrow = (lane & 7) + ((lane >> 3) & 1) * 8;
    int lcol = (lane >> 4) * 8;
    unsigned sAh = (unsigned)__cvta_generic_to_shared(As_h);
    unsigned sAl = (unsigned)__cvta_generic_to_shared(As_l);
    unsigned sBh = (unsigned)__cvta_generic_to_shared(Bs_h);
    unsigned sBl = (unsigned)__cvta_generic_to_shared(Bs_l);

    for (int kc = 0; kc < 128; kc += 32) {
        __syncthreads();
        // A tile [128 x 32] bf16 hi/lo
        {
            bool ok = (m0 + ar < NN);
            uint4 z = make_uint4(0u, 0u, 0u, 0u);
            const uint4* ph = (const uint4*)&g_ah[(m0 + ar) * 128 + kc + akg];
            const uint4* pl = (const uint4*)&g_al[(m0 + ar) * 128 + kc + akg];
            uint4 h0 = ok ? ph[0] : z, h1 = ok ? ph[1] : z;
            uint4 l0 = ok ? pl[0] : z, l1 = ok ? pl[1] : z;
            *(uint4*)&As_h[ar][akg]     = h0;
            *(uint4*)&As_h[ar][akg + 8] = h1;
            *(uint4*)&As_l[ar][akg]     = l0;
            *(uint4*)&As_l[ar][akg + 8] = l1;
        }
        // B tile [32 x 128] bf16 hi/lo
        {
            const uint4* ph = (const uint4*)&Bh[(kc + bkr) * 512 + h * 128 + bcg];
            const uint4* pl = (const uint4*)&Bl[(kc + bkr) * 512 + h * 128 + bcg];
            uint4 h0 = ph[0], h1 = ph[1];
            uint4 l0 = pl[0], l1 = pl[1];
            *(uint4*)&Bs_h[bkr][bcg]     = h0;
            *(uint4*)&Bs_h[bkr][bcg + 8] = h1;
            *(uint4*)&Bs_l[bkr][bcg]     = l0;
            *(uint4*)&Bs_l[bkr][bcg + 8] = l1;
        }
        __syncthreads();

#pragma unroll
        for (int kk = 0; kk < 32; kk += 16) {
            unsigned ah[2][4], al[2][4];
#pragma unroll
            for (int mt = 0; mt < 2; mt++) {
                unsigned off = (unsigned)(((warp_m * 32 + mt * 16 + lrow) * APAD + kk + lcol) * 2);
                ldsm_x4(ah[mt], sAh + off);
                ldsm_x4(al[mt], sAl + off);
            }
#pragma unroll
            for (int p = 0; p < 4; p++) {
                unsigned boff = (unsigned)(((kk + lrow) * BPAD + warp_n * 64 + p * 16 + lcol) * 2);
                unsigned bh[4], bl[4];
                ldsm_x4_t(bh, sBh + boff);
                ldsm_x4_t(bl, sBl + boff);
#pragma unroll
                for (int q = 0; q < 2; q++) {
#pragma unroll
                    for (int mt = 0; mt < 2; mt++) {
                        float* cc = c[mt][p * 2 + q];
                        mma_bf16(cc, ah[mt], &bh[q * 2]);
                        mma_bf16(cc, ah[mt], &bl[q * 2]);
                        mma_bf16(cc, al[mt], &bh[q * 2]);
                    }
                }
            }
        }
    }

    // epilogue: store C to g_hh + fused alpha partial dots
    float ps[4] = {0.f, 0.f, 0.f, 0.f}, pd[4] = {0.f, 0.f, 0.f, 0.f};
#pragma unroll
    for (int mt = 0; mt < 2; mt++) {
        int row0 = warp_m * 32 + mt * 16 + g;
        int row1 = row0 + 8;
#pragma unroll
        for (int nt = 0; nt < 8; nt++) {
            int col = warp_n * 64 + nt * 8 + t * 2;
            float c0 = c[mt][nt][0], c1 = c[mt][nt][1];
            float c2 = c[mt][nt][2], c3 = c[mt][nt][3];
            if (m0 + row0 < NN)
                *(float2*)&g_hh[(m0 + row0) * 512 + h * 128 + col] = make_float2(c0, c1);
            if (m0 + row1 < NN)
                *(float2*)&g_hh[(m0 + row1) * 512 + h * 128 + col] = make_float2(c2, c3);
            float w0 = s_as[col], w1 = s_as[col + 1];
            float d0 = s_ad[col], d1 = s_ad[col + 1];
            ps[mt * 2 + 0] += c0 * w0 + c1 * w1;
            ps[mt * 2 + 1] += c2 * w0 + c3 * w1;
            pd[mt * 2 + 0] += c0 * d0 + c1 * d1;
            pd[mt * 2 + 1] += c2 * d0 + c3 * d1;
        }
    }
#pragma unroll
    for (int off = 1; off <= 2; off <<= 1) {
#pragma unroll
        for (int i = 0; i < 4; i++) {
            ps[i] += __shfl_xor_sync(0xffffffffu, ps[i], off);
            pd[i] += __shfl_xor_sync(0xffffffffu, pd[i], off);
        }
    }
    if (t == 0) {
#pragma unroll
        for (int mt = 0; mt < 2; mt++)
#pragma unroll
            for (int hf = 0; hf < 2; hf++) {
                int row = warp_m * 32 + mt * 16 + hf * 8 + g;
                abuf[0][warp_n][row] = ps[mt * 2 + hf];
                abuf[1][warp_n][row] = pd[mt * 2 + hf];
            }
    }
    __syncthreads();
    if (tid < 128 && m0 + tid < NN) {
        g_as[(m0 + tid) * 4 + h] = abuf[0][0][tid] + abuf[0][1][tid];
        g_ad[(m0 + tid) * 4 + h] = abuf[1][0][tid] + abuf[1][1][tid];
    }
}

// ---------------- GAT aggregation + head-mean + bias + LN + relu + residual ----------------
__global__ __launch_bounds__(128) void k_gat(const float* __restrict__ bg,
                                             const float* __restrict__ lnw,
                                             const float* __restrict__ lnb) {
    int node = blockIdx.x, tid = threadIdx.x;
    int h = tid >> 5, lane = tid & 31;
    __shared__ float sm[4], ss[4], sad[4], rbuf[8];
    __shared__ int   ssrc[32];
    __shared__ float swt[32][4];
    if (tid < 4) sad[tid] = g_ad[node * 4 + tid];
    int beg = g_rowptr[node], end = g_rowptr[node + 1];
    __syncthreads();

    // pass 1: per-head online softmax stats (warp per head)
    float adh = sad[h];
    float m = -1e30f, s = 0.f;
    for (int e = beg + lane; e < end; e += 32) {
        int src = g_esrc[e];
        float x = g_as[src * 4 + h] + adh;
        x = x > 0.f ? x : 0.2f * x;
        float nm = fmaxf(m, x);
        s = s * __expf(m - nm) + __expf(x - nm);
        m = nm;
    }
#pragma unroll
    for (int off = 16; off > 0; off >>= 1) {
        float mo = __shfl_xor_sync(0xffffffffu, m, off);
        float so = __shfl_xor_sync(0xffffffffu, s, off);
        float nm = fmaxf(m, mo);
        s = s * __expf(m - nm) + so * __expf(mo - nm);
        m = nm;
    }
    if (lane == 0) { sm[h] = m; ss[h] = 1.f / s; }
    __syncthreads();

    // pass 2: chunked — compute each edge/head weight exactly once
    float c0 = 0.f, c1 = 0.f, c2 = 0.f, c3 = 0.f;
    for (int base = beg; base < end; base += 32) {
        int cnt = end - base; if (cnt > 32) cnt = 32;
        if (tid < cnt * 4) {
            int e  = base + (tid >> 2);
            int hd = tid & 3;
            int src = g_esrc[e];
            float x = g_as[src * 4 + hd] + sad[hd];
            x = x > 0.f ? x : 0.2f * x;
            swt[tid >> 2][hd] = __expf(x - sm[hd]) * ss[hd];
            if (hd == 0) ssrc[tid >> 2] = src;
        }
        __syncthreads();
        for (int j = 0; j < cnt; j++) {
            int src = ssrc[j];
            float4 w = *(const float4*)swt[j];
            const float* row = &g_hh[src * 512];
            c0 += w.x * row[tid];
            c1 += w.y * row[128 + tid];
            c2 += w.z * row[256 + tid];
            c3 += w.w * row[384 + tid];
        }
        __syncthreads();
    }
    float o = 0.25f * (c0 + c1 + c2 + c3) + bg[tid];

    // layernorm over 128 dims
    float vs = o, vq = o * o;
#pragma unroll
    for (int off = 16; off > 0; off >>= 1) {
        vs += __shfl_xor_sync(0xffffffffu, vs, off);
        vq += __shfl_xor_sync(0xffffffffu, vq, off);
    }
    if (lane == 0) { rbuf[h] = vs; rbuf[4 + h] = vq; }
    __syncthreads();
    float tot  = rbuf[0] + rbuf[1] + rbuf[2] + rbuf[3];
    float tot2 = rbuf[4] + rbuf[5] + rbuf[6] + rbuf[7];
    float mu  = tot * (1.f / 128.f);
    float var = tot2 * (1.f / 128.f) - mu * mu;
    float val = (o - mu) * rsqrtf(var + 1e-5f) * lnw[tid] + lnb[tid];
    float nv = g_h[node * DH + tid] + fmaxf(val, 0.f);
    g_h[node * DH + tid] = nv;
    __nv_bfloat16 hi = __float2bfloat16_rn(nv);
    g_ah[node * DH + tid] = hi;
    g_al[node * DH + tid] = __float2bfloat16_rn(nv - __bfloat162float(hi));
}

// ---------------- pooling (batch is sorted -> contiguous segments) ----------------
__global__ void k_pool() {
    int g = blockIdx.x, d = threadIdx.x;
    int beg = g_gstart[g], end = g_gstart[g + 1];
    float s = 0.f, mx = -1e30f;
    for (int i = beg; i < end; i++) {
        float v = g_h[i * DH + d];
        s += v;
        mx = fmaxf(mx, v);
    }
    int cnt = end - beg;
    float denom = (float)(cnt > 0 ? cnt : 1);
    g_pool[g * 320 + d]       = s / denom;
    g_pool[g * 320 + 128 + d] = (cnt > 0) ? mx : 0.f;
}

// ---------------- trunk + task heads (TDA branch fused in) ----------------
__global__ __launch_bounds__(256) void k_head(const float* __restrict__ tda,
                                              const float* __restrict__ wt1, const float* __restrict__ bt1,
                                              const float* __restrict__ wt2, const float* __restrict__ bt2,
                                              const float* __restrict__ wsh1, const float* __restrict__ bsh1,
                                              const float* __restrict__ wsh2, const float* __restrict__ bsh2,
                                              const float* __restrict__ wh1,  const float* __restrict__ bh1,
                                              const float* __restrict__ wh2,  const float* __restrict__ bh2,
                                              float* __restrict__ out) {
    int g = blockIdx.x, tid = threadIdx.x;
    __shared__ float comb[320], s1[256], s2[128], hh1[NT * 64], th1[64];
    for (int i = tid; i < 256; i += 256) comb[i] = g_pool[g * 320 + i];
    __syncthreads();
    if (tid < 64) {
        float a = bt1[tid];
#pragma unroll
        for (int k = 0; k < FT; k++) a += tda[g * FT + k] * wt1[k * 64 + tid];
        th1[tid] = fmaxf(a, 0.f);
    }
    __syncthreads();
    if (tid < 64) {
        float c = bt2[tid];
#pragma unroll
        for (int k = 0; k < 64; k++) c += th1[k] * wt2[k * 64 + tid];
        comb[256 + tid] = fmaxf(c, 0.f);
    }
    __syncthreads();
    float a = bsh1[tid];
    for (int k = 0; k < 320; k++) a += comb[k] * wsh1[k * 256 + tid];
    s1[tid] = fmaxf(a, 0.f);
    __syncthreads();
    if (tid < 128) {
        float c = bsh2[tid];
        for (int k = 0; k < 256; k++) c += s1[k] * wsh2[k * 128 + tid];
        s2[tid] = fmaxf(c, 0.f);
    }
    __syncthreads();
    for (int idx = tid; idx < NT * 64; idx += 256) {
        int t = idx >> 6, kk = idx & 63;
        float c = bh1[t * 64 + kk];
        for (int k = 0; k < 128; k++) c += s2[k] * wh1[t * 8192 + k * 64 + kk];
        hh1[idx] = fmaxf(c, 0.f);
    }
    __syncthreads();
    if (tid < NT) {
        float c = bh2[tid];
        for (int k = 0; k < 64; k++) c += hh1[tid * 64 + k] * wh2[tid * 64 + k];
        out[tid * NGR + g] = c;
    }
}

// ---------------- launch ----------------
extern "C" void kernel_launch(void* const* d_in, const int* in_sizes, int n_in,
                              void* d_out, int out_size) {
    const float* x       = (const float*)d_in[0];
    const int*   ei      = (const int*)d_in[1];
    const int*   batch   = (const int*)d_in[2];
    const float* tda     = (const float*)d_in[3];
    const float* w_in    = (const float*)d_in[4];
    const float* b_in    = (const float*)d_in[5];
    const float* w_gat   = (const float*)d_in[6];
    const float* a_src   = (const float*)d_in[7];
    const float* a_dst   = (const float*)d_in[8];
    const float* b_gat   = (const float*)d_in[9];
    const float* ln_w    = (const float*)d_in[10];
    const float* ln_b    = (const float*)d_in[11];
    const float* w_tda1  = (const float*)d_in[12];
    const float* b_tda1  = (const float*)d_in[13];
    const float* w_tda2  = (const float*)d_in[14];
    const float* b_tda2  = (const float*)d_in[15];
    const float* w_sh1   = (const float*)d_in[16];
    const float* b_sh1   = (const float*)d_in[17];
    const float* w_sh2   = (const float*)d_in[18];
    const float* b_sh2   = (const float*)d_in[19];
    const float* w_h1    = (const float*)d_in[20];
    const float* b_h1    = (const float*)d_in[21];
    const float* w_h2    = (const float*)d_in[22];
    const float* b_h2    = (const float*)d_in[23];
    float* out = (float*)d_out;

    // order keeps k_gemm_tc at launch index 3 (ncu profiled slot)
    k_wsplit<<<(NL * DH * NH * DH + 255) / 256, 256>>>(w_gat);  // 0
    k_inproj<<<NN, 128>>>(x, w_in, b_in);                       // 1
    k_prep<<<(NN + 256) / 256, 256>>>(batch);                   // 2
    k_gemm_tc<<<dim3((NN + 127) / 128, 4), 256>>>(0, a_src, a_dst);  // 3 (layer 0 GEMM)
    k_count<<<(ETOT + 255) / 256, 256>>>(ei);                   // 4
    k_scan<<<1, 1024>>>();                                      // 5
    k_scatter<<<(ETOT + 255) / 256, 256>>>(ei);                 // 6
    k_gat<<<NN, 128>>>(b_gat, ln_w, ln_b);                      // 7 (layer 0 agg)

    for (int l = 1; l < NL; l++) {
        k_gemm_tc<<<dim3((NN + 127) / 128, 4), 256>>>(l, a_src + l * 512, a_dst + l * 512);
        k_gat<<<NN, 128>>>(b_gat + l * 128, ln_w + l * 128, ln_b + l * 128);
    }

    // pooling + fused TDA/trunk/heads
    k_pool<<<NGR, 128>>>();
    k_head<<<NGR, 256>>>(tda, w_tda1, b_tda1, w_tda2, b_tda2,
                         w_sh1, b_sh1, w_sh2, b_sh2, w_h1, b_h1, w_h2, b_h2, out);
}